// round 2
// baseline (speedup 1.0000x reference)
#include <cuda_runtime.h>

// Problem constants: B=128, N=1024.
// Output[b, k] where k enumerates strict-upper-triangle pairs (i,j), j>i,
// row-major: row i starts at off(i) = i*(N-1) - i*(i-1)/2, value = a[b,j]-a[b,i].

constexpr int N_ELEM  = 1024;
constexpr int M_PAIRS = N_ELEM * (N_ELEM - 1) / 2;   // 523776
constexpr int M4      = M_PAIRS / 4;                 // 130944 (divisible by 4)
constexpr int THREADS = 256;
constexpr int IPT     = 4;                           // float4s per thread
constexpr int K4_PER_BLOCK = THREADS * IPT;          // 1024

__device__ __forceinline__ int row_off(int i) {
    // offset of first element of row i in the flattened upper triangle
    return i * (N_ELEM - 1) - ((i * (i - 1)) >> 1);
}

__global__ __launch_bounds__(THREADS)
void relpos_kernel(const float* __restrict__ in, float* __restrict__ out) {
    __shared__ float s[N_ELEM];

    const int b = blockIdx.y;
    const float* a = in + (size_t)b * N_ELEM;

    // Stage this batch's 4KB input row into shared memory (vectorized).
    {
        const float4* a4 = reinterpret_cast<const float4*>(a);
        float4* s4 = reinterpret_cast<float4*>(s);
        // N_ELEM/4 = 256 == THREADS: exactly one float4 per thread
        s4[threadIdx.x] = a4[threadIdx.x];
    }
    __syncthreads();

    float4* outb = reinterpret_cast<float4*>(out + (size_t)b * M_PAIRS);
    const int base = blockIdx.x * K4_PER_BLOCK + threadIdx.x;

    #pragma unroll
    for (int it = 0; it < IPT; it++) {
        const int k4 = base + it * THREADS;
        if (k4 >= M4) continue;      // only last x-block is partial

        const int k = k4 << 2;       // first of 4 consecutive pair-indices

        // Closed-form row index: solve off(i) <= k < off(i+1).
        // i = floor((t - sqrt(t^2 - 8k)) / 2), t = 2N-1 = 2047.
        // disc <= 2047^2 = 4190209 < 2^24 -> exact in fp32; fixup handles rounding.
        const int disc = 2047 * 2047 - (k << 3);
        int i = (int)(0.5f * (2047.0f - sqrtf((float)disc)));
        if (i < 0) i = 0;
        while (row_off(i + 1) <= k) ++i;
        while (row_off(i) > k) --i;

        int j = i + 1 + (k - row_off(i));
        float ai = s[i];

        float r0, r1, r2, r3;
        r0 = s[j] - ai; if (++j == N_ELEM) { ++i; j = i + 1; ai = s[i]; }
        r1 = s[j] - ai; if (++j == N_ELEM) { ++i; j = i + 1; ai = s[i]; }
        r2 = s[j] - ai; if (++j == N_ELEM) { ++i; j = i + 1; ai = s[i]; }
        r3 = s[j] - ai;

        outb[k4] = make_float4(r0, r1, r2, r3);
    }
}

extern "C" void kernel_launch(void* const* d_in, const int* in_sizes, int n_in,
                              void* d_out, int out_size) {
    const float* in = (const float*)d_in[0];
    float* out = (float*)d_out;
    const int B = in_sizes[0] / N_ELEM;   // 128

    dim3 grid((M4 + K4_PER_BLOCK - 1) / K4_PER_BLOCK, B);  // (128, 128)
    relpos_kernel<<<grid, THREADS>>>(in, out);
}